// round 7
// baseline (speedup 1.0000x reference)
#include <cuda_runtime.h>
#include <cuda_fp16.h>
#include <mma.h>

using namespace nvcuda;

#define NMAX 100000
#define EMAX 1600000
#define CIN  128

// ---------------- scratch (device globals; no allocation allowed) ----------
__device__ int   g_deg[NMAX];          // degree incl self-loop
__device__ int   g_offs[NMAX];         // CSR start (block-atomic bases; end = start+deg-1)
__device__ int   g_cursor[NMAX];
__device__ int   g_base;               // atomic base for block scan
__device__ __align__(16) int2   g_csr[EMAX];        // {src, float bits of norm}
__device__ __align__(16) __half g_h[NMAX * 64];     // gemm output, fp16 (layer3 pitch 40)
__device__ __align__(16) __half g_out_h[NMAX * 64]; // agg output, fp16, RELU APPLIED

// ---------------- prep -------------------------------------------------------
__global__ void k_init(int n) {
    int i = blockIdx.x * blockDim.x + threadIdx.x;
    if (i < n) g_deg[i] = 1;  // self loop
    if (i == 0) g_base = 0;
}

__global__ void k_count(const int* __restrict__ ei, int E) {
    int e = blockIdx.x * blockDim.x + threadIdx.x;
    if (e < E) {
        int d = ei[E + e];
        atomicAdd(&g_deg[d], 1);
    }
}

// single-kernel scan of (deg-1): block-local scan + atomic base.
__global__ void k_scan(int n) {
    __shared__ int wsum[8];
    __shared__ int sbase;
    int t = threadIdx.x;
    int lane = t & 31, wid = t >> 5;
    int base = blockIdx.x * 1024;
    int loc[4];
    int v = 0;
    #pragma unroll
    for (int j = 0; j < 4; j++) {
        int i = base + t * 4 + j;
        loc[j] = (i < n) ? (g_deg[i] - 1) : 0;
        v += loc[j];
    }
    int s = v;
    #pragma unroll
    for (int off = 1; off < 32; off <<= 1) {
        int y = __shfl_up_sync(0xffffffffu, s, off);
        if (lane >= off) s += y;
    }
    if (lane == 31) wsum[wid] = s;
    __syncthreads();
    if (t == 0) {
        int acc = 0;
        #pragma unroll
        for (int w = 0; w < 8; w++) { int x2 = wsum[w]; wsum[w] = acc; acc += x2; }
        sbase = atomicAdd(&g_base, acc);
    }
    __syncthreads();
    int run = sbase + wsum[wid] + s - v;
    #pragma unroll
    for (int j = 0; j < 4; j++) {
        int i = base + t * 4 + j;
        if (i < n) {
            g_offs[i] = run;
            g_cursor[i] = run;
            run += loc[j];
        }
    }
}

__global__ void k_fill_csr(const int* __restrict__ ei, int E) {
    int e = blockIdx.x * blockDim.x + threadIdx.x;
    if (e < E) {
        int s = ei[e];
        int d = ei[E + e];
        float norm = rsqrtf((float)g_deg[s]) * rsqrtf((float)g_deg[d]);
        int pos = atomicAdd(&g_cursor[d], 1);
        g_csr[pos] = make_int2(s, __float_as_int(norm));
    }
}

// ---------------- layer-1 GEMM (fp32 SIMT; hidden behind prep) ---------------
// g_h(fp16) = x(fp32) @ W1
__global__ void k_gemm1(const float* __restrict__ X, const float* __restrict__ W,
                        int n) {
    constexpr int K = 128, COUT = 64, BM = 32;
    constexpr int NT = COUT / 4;     // 16
    constexpr int NTHREADS = NT * (BM / 4);  // 128
    __shared__ float ws[K][COUT];
    __shared__ float xs[BM][K];

    int t = threadIdx.x;
    constexpr int WF4 = K * COUT / 4;
    float* wsf = &ws[0][0];
    for (int idx = t; idx < WF4; idx += NTHREADS)
        *(float4*)&wsf[idx * 4] = *(const float4*)&W[idx * 4];

    int nidx = t % NT;
    int midx = t / NT;
    int ntiles = (n + BM - 1) / BM;

    for (int tile = blockIdx.x; tile < ntiles; tile += gridDim.x) {
        int base = tile * BM;
        __syncthreads();
        constexpr int XF4 = BM * K / 4;
        for (int idx = t; idx < XF4; idx += NTHREADS) {
            int r = idx / (K / 4), kc = idx % (K / 4);
            int gr = base + r;
            float4 v = make_float4(0.f, 0.f, 0.f, 0.f);
            if (gr < n) v = *(const float4*)&X[(size_t)gr * K + kc * 4];
            *(float4*)&xs[r][kc * 4] = v;
        }
        __syncthreads();

        float acc[4][4] = {};
        #pragma unroll 8
        for (int k = 0; k < K; k++) {
            float4 b4 = *(float4*)&ws[k][nidx * 4];
            float a0 = xs[midx * 4 + 0][k];
            float a1 = xs[midx * 4 + 1][k];
            float a2 = xs[midx * 4 + 2][k];
            float a3 = xs[midx * 4 + 3][k];
            acc[0][0] += a0 * b4.x; acc[0][1] += a0 * b4.y; acc[0][2] += a0 * b4.z; acc[0][3] += a0 * b4.w;
            acc[1][0] += a1 * b4.x; acc[1][1] += a1 * b4.y; acc[1][2] += a1 * b4.z; acc[1][3] += a1 * b4.w;
            acc[2][0] += a2 * b4.x; acc[2][1] += a2 * b4.y; acc[2][2] += a2 * b4.z; acc[2][3] += a2 * b4.w;
            acc[3][0] += a3 * b4.x; acc[3][1] += a3 * b4.y; acc[3][2] += a3 * b4.z; acc[3][3] += a3 * b4.w;
        }

        #pragma unroll
        for (int i = 0; i < 4; i++) {
            int gr = base + midx * 4 + i;
            if (gr < n) {
                __half2 p0 = __floats2half2_rn(acc[i][0], acc[i][1]);
                __half2 p1 = __floats2half2_rn(acc[i][2], acc[i][3]);
                uint2 u = make_uint2(*(unsigned*)&p0, *(unsigned*)&p1);
                *(uint2*)&g_h[(size_t)gr * COUT + nidx * 4] = u;
            }
        }
    }
}

// ---------------- wmma GEMM (layers 2/3): g_h = g_out_h(relu'd fp16) @ W ----
// A [n,64] fp16, W fp32 -> smem fp16, C fp16 with fp32 accum via smem staging.
template <int CT>  // CT = cout tiles of 16; COUT_PAD = 16*CT
__global__ void k_gemm_wmma(const float* __restrict__ W, int n, int coutReal) {
    constexpr int K = 64;
    constexpr int CP = 16 * CT;              // padded cout
    constexpr int NWARP = 8;                 // 256 threads
    __shared__ __half wsh[K][CP];
    __shared__ float  osh[NWARP][16][CP];

    int t = threadIdx.x;
    int warp = t >> 5, lane = t & 31;

    // zero-pad + load W (fp32 -> fp16)
    for (int idx = t; idx < K * CP; idx += 256) wsh[idx / CP][idx % CP] = __float2half(0.f);
    __syncthreads();
    for (int idx = t; idx < K * coutReal; idx += 256) {
        int k = idx / coutReal, c = idx % coutReal;
        wsh[k][c] = __float2half(W[idx]);
    }
    __syncthreads();

    const __half* A = (const __half*)g_out_h;
    int ntiles = (n + 15) / 16;

    for (int tile = blockIdx.x * NWARP + warp; tile < ntiles; tile += gridDim.x * NWARP) {
        int row = tile * 16;
        wmma::fragment<wmma::accumulator, 16, 16, 16, float> acc[CT];
        #pragma unroll
        for (int c = 0; c < CT; c++) wmma::fill_fragment(acc[c], 0.f);

        #pragma unroll
        for (int kt = 0; kt < K / 16; kt++) {
            wmma::fragment<wmma::matrix_a, 16, 16, 16, __half, wmma::row_major> a;
            wmma::load_matrix_sync(a, &A[(size_t)row * K + kt * 16], K);
            #pragma unroll
            for (int c = 0; c < CT; c++) {
                wmma::fragment<wmma::matrix_b, 16, 16, 16, __half, wmma::row_major> b;
                wmma::load_matrix_sync(b, &wsh[kt * 16][c * 16], CP);
                wmma::mma_sync(acc[c], a, b, acc[c]);
            }
        }
        #pragma unroll
        for (int c = 0; c < CT; c++)
            wmma::store_matrix_sync(&osh[warp][0][c * 16], acc[c], CP, wmma::mem_row_major);
        __syncwarp();

        int half2PerRow = coutReal / 2;
        for (int idx = lane; idx < 16 * half2PerRow; idx += 32) {
            int r = idx / half2PerRow, cc = idx % half2PerRow;
            __half2 p = __floats2half2_rn(osh[warp][r][cc * 2], osh[warp][r][cc * 2 + 1]);
            *(unsigned*)&g_h[(size_t)(row + r) * coutReal + cc * 2] = *(unsigned*)&p;
        }
        __syncwarp();
    }
}

// ---------------- aggregation: out = b + h[i]/deg + sum norm*h[src] ---------
// grid-stride warps; lane owns 2 channels; unroll 8 for MLP.
// FINAL: write fp32 OUT arg; else write relu(out) as fp16 to g_out_h.
template <int C, bool FINAL>
__global__ void k_agg(const float* __restrict__ b, float* __restrict__ OUTarg,
                      int n) {
    const __half* H = (const __half*)g_h;

    int warp0 = (blockIdx.x * blockDim.x + threadIdx.x) >> 5;
    int nwarps = (gridDim.x * blockDim.x) >> 5;
    int lane = threadIdx.x & 31;
    int c = lane * 2;
    bool act = (c < C);
    float bx = 0.f, by = 0.f;
    if (act) { bx = b[c]; by = b[c + 1]; }

    for (int node = warp0; node < n; node += nwarps) {
        int deg = g_deg[node];
        float2 acc = make_float2(0.f, 0.f);
        if (act) {
            float2 hv = __half22float2(*(const __half2*)&H[(size_t)node * C + c]);
            float w = 1.0f / (float)deg;
            acc.x = bx + w * hv.x;
            acc.y = by + w * hv.y;
        }

        int e0 = g_offs[node];
        int e1 = e0 + deg - 1;
        int e = e0;
        for (; e + 8 <= e1; e += 8) {
            int2 r[8];
            #pragma unroll
            for (int j = 0; j < 8; j++) r[j] = g_csr[e + j];
            if (act) {
                #pragma unroll
                for (int j = 0; j < 8; j++) {
                    float2 hv = __half22float2(*(const __half2*)&H[(size_t)r[j].x * C + c]);
                    float nn = __int_as_float(r[j].y);
                    acc.x += nn * hv.x; acc.y += nn * hv.y;
                }
            }
        }
        for (; e < e1; e++) {
            int2 r = g_csr[e];
            if (act) {
                float2 hv = __half22float2(*(const __half2*)&H[(size_t)r.x * C + c]);
                float nn = __int_as_float(r.y);
                acc.x += nn * hv.x; acc.y += nn * hv.y;
            }
        }
        if (act) {
            if (FINAL) {
                *(float2*)&OUTarg[(size_t)node * C + c] = acc;
            } else {
                // fused ReLU for next layer's GEMM
                acc.x = fmaxf(acc.x, 0.f);
                acc.y = fmaxf(acc.y, 0.f);
                __half2 p = __floats2half2_rn(acc.x, acc.y);
                *(unsigned*)&g_out_h[(size_t)node * C + c] = *(unsigned*)&p;
            }
        }
    }
}

// ---------------- launcher ---------------------------------------------------
extern "C" void kernel_launch(void* const* d_in, const int* in_sizes, int n_in,
                              void* d_out, int out_size) {
    const float* x  = (const float*)d_in[0];
    const int*   ei = (const int*)d_in[1];
    const float* W1 = (const float*)d_in[2];
    const float* b1 = (const float*)d_in[3];
    const float* W2 = (const float*)d_in[4];
    const float* b2 = (const float*)d_in[5];
    const float* W3 = (const float*)d_in[6];
    const float* b3 = (const float*)d_in[7];
    float* out = (float*)d_out;

    int n = in_sizes[0] / CIN;
    int E = in_sizes[1] / 2;
    if (n > NMAX) n = NMAX;
    if (E > EMAX) E = EMAX;
    int nb = (n + 1023) / 1024;

    static cudaStream_t s2 = nullptr;
    static cudaEvent_t evFork = nullptr, evJoin = nullptr;
    if (!s2) {
        cudaStreamCreate(&s2);
        cudaEventCreateWithFlags(&evFork, cudaEventDisableTiming);
        cudaEventCreateWithFlags(&evJoin, cudaEventDisableTiming);
    }

    // fork: prep chain on s2, GEMM1 on main stream
    cudaEventRecord(evFork, 0);
    cudaStreamWaitEvent(s2, evFork, 0);

    k_init<<<(n + 255) / 256, 256, 0, s2>>>(n);
    k_count<<<(E + 255) / 256, 256, 0, s2>>>(ei, E);
    k_scan<<<nb, 256, 0, s2>>>(n);
    k_fill_csr<<<(E + 255) / 256, 256, 0, s2>>>(ei, E);
    cudaEventRecord(evJoin, s2);

    // layer 1 GEMM: x[128] -> 64 (independent of CSR prep; hidden behind it)
    k_gemm1<<<592, 128>>>(x, W1, n);

    cudaStreamWaitEvent(0, evJoin, 0);

    int agg_grid = 1184;
    int wmma_grid = ((n + 15) / 16 + 7) / 8;  // one 16-row tile per warp

    k_agg<64, false><<<agg_grid, 256>>>(b1, nullptr, n);         // + relu
    k_gemm_wmma<4><<<wmma_grid, 256>>>(W2, n, 64);
    k_agg<64, false><<<agg_grid, 256>>>(b2, nullptr, n);         // + relu
    k_gemm_wmma<3><<<wmma_grid, 256>>>(W3, n, 40);
    k_agg<40, true><<<agg_grid, 256>>>(b3, out, n);
}

// round 8
// speedup vs baseline: 1.1191x; 1.1191x over previous
#include <cuda_runtime.h>
#include <cuda_fp16.h>

#define NMAX 100000
#define EMAX 1600000
#define CIN  128

// ---------------- scratch (device globals; no allocation allowed) ----------
__device__ int   g_deg[NMAX];          // degree incl self-loop
__device__ int   g_offs[NMAX];         // CSR start (block-atomic bases; end = start+deg-1)
__device__ int   g_cursor[NMAX];
__device__ int   g_base;               // atomic base for block scan
__device__ __align__(16) int2   g_csr[EMAX];        // {src, float bits of dinv[src]}
__device__ __align__(16) __half g_h[NMAX * 64];     // gemm output, fp16 (layer3 pitch 40)
__device__ __align__(16) __half g_out_h[NMAX * 64]; // agg output, fp16, RELU APPLIED

// ---------------- prep -------------------------------------------------------
__global__ void k_init(int n) {
    int i = blockIdx.x * blockDim.x + threadIdx.x;
    if (i < n) g_deg[i] = 1;  // self loop
    if (i == 0) g_base = 0;
}

__global__ void k_count(const int* __restrict__ ei, int E) {
    int e = blockIdx.x * blockDim.x + threadIdx.x;
    if (e < E) {
        int d = ei[E + e];
        atomicAdd(&g_deg[d], 1);
    }
}

// single-kernel scan of (deg-1): block-local scan + atomic base.
__global__ void k_scan(int n) {
    __shared__ int wsum[8];
    __shared__ int sbase;
    int t = threadIdx.x;
    int lane = t & 31, wid = t >> 5;
    int base = blockIdx.x * 1024;
    int loc[4];
    int v = 0;
    #pragma unroll
    for (int j = 0; j < 4; j++) {
        int i = base + t * 4 + j;
        loc[j] = (i < n) ? (g_deg[i] - 1) : 0;
        v += loc[j];
    }
    int s = v;
    #pragma unroll
    for (int off = 1; off < 32; off <<= 1) {
        int y = __shfl_up_sync(0xffffffffu, s, off);
        if (lane >= off) s += y;
    }
    if (lane == 31) wsum[wid] = s;
    __syncthreads();
    if (t == 0) {
        int acc = 0;
        #pragma unroll
        for (int w = 0; w < 8; w++) { int x2 = wsum[w]; wsum[w] = acc; acc += x2; }
        sbase = atomicAdd(&g_base, acc);
    }
    __syncthreads();
    int run = sbase + wsum[wid] + s - v;
    #pragma unroll
    for (int j = 0; j < 4; j++) {
        int i = base + t * 4 + j;
        if (i < n) {
            g_offs[i] = run;
            g_cursor[i] = run;
            run += loc[j];
        }
    }
}

// CSR fill: store {src, dinv[src]} only — dinv[dst] is factored out and applied
// once per node in the aggregation epilogue.
__global__ void k_fill_csr(const int* __restrict__ ei, int E) {
    int e = blockIdx.x * blockDim.x + threadIdx.x;
    if (e < E) {
        int s = ei[e];
        int d = ei[E + e];
        float ds = rsqrtf((float)g_deg[s]);
        int pos = atomicAdd(&g_cursor[d], 1);
        g_csr[pos] = make_int2(s, __float_as_int(ds));
    }
}

// ---------------- layer-1 GEMM (fp32 SIMT persistent; hidden behind prep) ---
// g_h(fp16) = x(fp32) @ W1
__global__ void k_gemm1(const float* __restrict__ X, const float* __restrict__ W,
                        int n) {
    constexpr int K = 128, COUT = 64, BM = 32;
    constexpr int NT = COUT / 4;             // 16
    constexpr int NTHREADS = NT * (BM / 4);  // 128
    __shared__ float ws[K][COUT];
    __shared__ float xs[BM][K];

    int t = threadIdx.x;
    constexpr int WF4 = K * COUT / 4;
    float* wsf = &ws[0][0];
    for (int idx = t; idx < WF4; idx += NTHREADS)
        *(float4*)&wsf[idx * 4] = *(const float4*)&W[idx * 4];

    int nidx = t % NT;
    int midx = t / NT;
    int ntiles = (n + BM - 1) / BM;

    for (int tile = blockIdx.x; tile < ntiles; tile += gridDim.x) {
        int base = tile * BM;
        __syncthreads();
        constexpr int XF4 = BM * K / 4;
        for (int idx = t; idx < XF4; idx += NTHREADS) {
            int r = idx / (K / 4), kc = idx % (K / 4);
            int gr = base + r;
            float4 v = make_float4(0.f, 0.f, 0.f, 0.f);
            if (gr < n) v = *(const float4*)&X[(size_t)gr * K + kc * 4];
            *(float4*)&xs[r][kc * 4] = v;
        }
        __syncthreads();

        float acc[4][4] = {};
        #pragma unroll 8
        for (int k = 0; k < K; k++) {
            float4 b4 = *(float4*)&ws[k][nidx * 4];
            float a0 = xs[midx * 4 + 0][k];
            float a1 = xs[midx * 4 + 1][k];
            float a2 = xs[midx * 4 + 2][k];
            float a3 = xs[midx * 4 + 3][k];
            acc[0][0] += a0 * b4.x; acc[0][1] += a0 * b4.y; acc[0][2] += a0 * b4.z; acc[0][3] += a0 * b4.w;
            acc[1][0] += a1 * b4.x; acc[1][1] += a1 * b4.y; acc[1][2] += a1 * b4.z; acc[1][3] += a1 * b4.w;
            acc[2][0] += a2 * b4.x; acc[2][1] += a2 * b4.y; acc[2][2] += a2 * b4.z; acc[2][3] += a2 * b4.w;
            acc[3][0] += a3 * b4.x; acc[3][1] += a3 * b4.y; acc[3][2] += a3 * b4.z; acc[3][3] += a3 * b4.w;
        }

        #pragma unroll
        for (int i = 0; i < 4; i++) {
            int gr = base + midx * 4 + i;
            if (gr < n) {
                __half2 p0 = __floats2half2_rn(acc[i][0], acc[i][1]);
                __half2 p1 = __floats2half2_rn(acc[i][2], acc[i][3]);
                uint2 u = make_uint2(*(unsigned*)&p0, *(unsigned*)&p1);
                *(uint2*)&g_h[(size_t)gr * COUT + nidx * 4] = u;
            }
        }
    }
}

// ---------------- layers 2/3 GEMM (SIMT persistent, fp16 in/out) ------------
// g_h(fp16) = g_out_h(fp16, relu'd) @ W(fp32)
template <int K, int COUT>
__global__ void k_gemm_h(const float* __restrict__ W, int n) {
    constexpr int BM = 32;
    constexpr int NT = COUT / 4;
    constexpr int MT = BM / 4;               // 8
    constexpr int NTHREADS = NT * MT;
    __shared__ float ws[K][COUT];
    __shared__ float xs[BM][K];

    int t = threadIdx.x;
    constexpr int WF4 = K * COUT / 4;
    float* wsf = &ws[0][0];
    for (int idx = t; idx < WF4; idx += NTHREADS)
        *(float4*)&wsf[idx * 4] = *(const float4*)&W[idx * 4];

    int nidx = t % NT;
    int midx = t / NT;
    int ntiles = (n + BM - 1) / BM;

    for (int tile = blockIdx.x; tile < ntiles; tile += gridDim.x) {
        int base = tile * BM;
        __syncthreads();
        constexpr int XF4 = BM * K / 4;      // float4 = 4 floats = one uint2 of halves
        for (int idx = t; idx < XF4; idx += NTHREADS) {
            int r = idx / (K / 4), kc = idx % (K / 4);
            int gr = base + r;
            float4 v = make_float4(0.f, 0.f, 0.f, 0.f);
            if (gr < n) {
                uint2 u = *(const uint2*)&g_out_h[(size_t)gr * K + kc * 4];
                float2 f01 = __half22float2(*(__half2*)&u.x);
                float2 f23 = __half22float2(*(__half2*)&u.y);
                v = make_float4(f01.x, f01.y, f23.x, f23.y);
            }
            *(float4*)&xs[r][kc * 4] = v;
        }
        __syncthreads();

        float acc[4][4] = {};
        #pragma unroll 8
        for (int k = 0; k < K; k++) {
            float4 b4 = *(float4*)&ws[k][nidx * 4];
            float a0 = xs[midx * 4 + 0][k];
            float a1 = xs[midx * 4 + 1][k];
            float a2 = xs[midx * 4 + 2][k];
            float a3 = xs[midx * 4 + 3][k];
            acc[0][0] += a0 * b4.x; acc[0][1] += a0 * b4.y; acc[0][2] += a0 * b4.z; acc[0][3] += a0 * b4.w;
            acc[1][0] += a1 * b4.x; acc[1][1] += a1 * b4.y; acc[1][2] += a1 * b4.z; acc[1][3] += a1 * b4.w;
            acc[2][0] += a2 * b4.x; acc[2][1] += a2 * b4.y; acc[2][2] += a2 * b4.z; acc[2][3] += a2 * b4.w;
            acc[3][0] += a3 * b4.x; acc[3][1] += a3 * b4.y; acc[3][2] += a3 * b4.z; acc[3][3] += a3 * b4.w;
        }

        #pragma unroll
        for (int i = 0; i < 4; i++) {
            int gr = base + midx * 4 + i;
            if (gr < n) {
                __half2 p0 = __floats2half2_rn(acc[i][0], acc[i][1]);
                __half2 p1 = __floats2half2_rn(acc[i][2], acc[i][3]);
                uint2 u = make_uint2(*(unsigned*)&p0, *(unsigned*)&p1);
                *(uint2*)&g_h[(size_t)gr * COUT + nidx * 4] = u;
            }
        }
    }
}

// ---------------- aggregation ------------------------------------------------
// out = b + dinv_d * (dinv_d*h[node] + sum_s dinv_s*h[s])
// one warp per node; lane owns 2 channels; edge record broadcast-loaded;
// unroll 4. FINAL: fp32 OUT arg; else relu -> fp16 g_out_h.
template <int C, bool FINAL>
__global__ void k_agg(const float* __restrict__ b, float* __restrict__ OUTarg,
                      int n) {
    const __half* H = (const __half*)g_h;

    int node = (blockIdx.x * blockDim.x + threadIdx.x) >> 5;
    int lane = threadIdx.x & 31;
    if (node >= n) return;
    int c = lane * 2;
    bool act = (c < C);

    int deg = g_deg[node];
    float dinv = rsqrtf((float)deg);

    float2 acc = make_float2(0.f, 0.f);
    if (act) {
        float2 hv = __half22float2(*(const __half2*)&H[(size_t)node * C + c]);
        acc.x = dinv * hv.x;   // self-loop contribution (pre dinv_d scaling)
        acc.y = dinv * hv.y;
    }

    int e0 = g_offs[node];
    int e1 = e0 + deg - 1;
    int e = e0;
    for (; e + 4 <= e1; e += 4) {
        int2 r0 = g_csr[e];
        int2 r1 = g_csr[e + 1];
        int2 r2 = g_csr[e + 2];
        int2 r3 = g_csr[e + 3];
        if (act) {
            float2 h0 = __half22float2(*(const __half2*)&H[(size_t)r0.x * C + c]);
            float2 h1 = __half22float2(*(const __half2*)&H[(size_t)r1.x * C + c]);
            float2 h2 = __half22float2(*(const __half2*)&H[(size_t)r2.x * C + c]);
            float2 h3 = __half22float2(*(const __half2*)&H[(size_t)r3.x * C + c]);
            float n0 = __int_as_float(r0.y), n1 = __int_as_float(r1.y);
            float n2 = __int_as_float(r2.y), n3 = __int_as_float(r3.y);
            acc.x += n0 * h0.x; acc.y += n0 * h0.y;
            acc.x += n1 * h1.x; acc.y += n1 * h1.y;
            acc.x += n2 * h2.x; acc.y += n2 * h2.y;
            acc.x += n3 * h3.x; acc.y += n3 * h3.y;
        }
    }
    for (; e < e1; e++) {
        int2 r = g_csr[e];
        if (act) {
            float2 hv = __half22float2(*(const __half2*)&H[(size_t)r.x * C + c]);
            float nn = __int_as_float(r.y);
            acc.x += nn * hv.x; acc.y += nn * hv.y;
        }
    }
    if (act) {
        float ox = b[c]     + dinv * acc.x;
        float oy = b[c + 1] + dinv * acc.y;
        if (FINAL) {
            *(float2*)&OUTarg[(size_t)node * C + c] = make_float2(ox, oy);
        } else {
            ox = fmaxf(ox, 0.f);
            oy = fmaxf(oy, 0.f);
            __half2 p = __floats2half2_rn(ox, oy);
            *(unsigned*)&g_out_h[(size_t)node * C + c] = *(unsigned*)&p;
        }
    }
}

// ---------------- launcher ---------------------------------------------------
extern "C" void kernel_launch(void* const* d_in, const int* in_sizes, int n_in,
                              void* d_out, int out_size) {
    const float* x  = (const float*)d_in[0];
    const int*   ei = (const int*)d_in[1];
    const float* W1 = (const float*)d_in[2];
    const float* b1 = (const float*)d_in[3];
    const float* W2 = (const float*)d_in[4];
    const float* b2 = (const float*)d_in[5];
    const float* W3 = (const float*)d_in[6];
    const float* b3 = (const float*)d_in[7];
    float* out = (float*)d_out;

    int n = in_sizes[0] / CIN;
    int E = in_sizes[1] / 2;
    if (n > NMAX) n = NMAX;
    if (E > EMAX) E = EMAX;
    int nb = (n + 1023) / 1024;

    static cudaStream_t s2 = nullptr;
    static cudaEvent_t evFork = nullptr, evJoin = nullptr;
    if (!s2) {
        cudaStreamCreate(&s2);
        cudaEventCreateWithFlags(&evFork, cudaEventDisableTiming);
        cudaEventCreateWithFlags(&evJoin, cudaEventDisableTiming);
    }

    // fork: prep chain on s2, GEMM1 on main stream
    cudaEventRecord(evFork, 0);
    cudaStreamWaitEvent(s2, evFork, 0);

    k_init<<<(n + 255) / 256, 256, 0, s2>>>(n);
    k_count<<<(E + 255) / 256, 256, 0, s2>>>(ei, E);
    k_scan<<<nb, 256, 0, s2>>>(n);
    k_fill_csr<<<(E + 255) / 256, 256, 0, s2>>>(ei, E);
    cudaEventRecord(evJoin, s2);

    // layer 1 GEMM: x[128] -> 64 (independent of CSR prep; hidden behind it)
    k_gemm1<<<592, 128>>>(x, W1, n);

    cudaStreamWaitEvent(0, evJoin, 0);

    int agg_grid = (n + 7) / 8;   // one warp per node, 8 warps/block

    k_agg<64, false><<<agg_grid, 256>>>(b1, nullptr, n);   // + relu
    k_gemm_h<64, 64><<<1184, 128>>>(W2, n);
    k_agg<64, false><<<agg_grid, 256>>>(b2, nullptr, n);   // + relu
    k_gemm_h<64, 40><<<1184, 80>>>(W3, n);
    k_agg<40, true><<<agg_grid, 256>>>(b3, out, n);
}